// round 5
// baseline (speedup 1.0000x reference)
#include <cuda_runtime.h>
#include <cstdint>
#include <cstddef>

// ---------------- device scratch (static, no runtime alloc) ----------------
__device__ float g_preF[(size_t)1024 * 64 * 2048];      // x@Wf[:512]+bf, time-major [t][b][g]
__device__ float g_preB[(size_t)1024 * 64 * 2048];      // x@Wb[:512]+bb
__device__ float g_base[2][256][2048];                  // embed@W[:512] per vocab entry
__device__ uint2 g_dropPack[(size_t)65536 * 128];       // per row: (d, bits(e[tok][d])) dropped entries
__device__ unsigned int g_dropN[65536];                 // per row: dropped count
__device__ unsigned char g_zb[(size_t)2 * 1024 * 32768];// zoneout bits: bit0=keep h, bit1=keep c
__device__ uint2 g_kz[2 * 1024];                        // per-step zoneout keys (fwd, bwd)
__device__ uint2 g_kd;                                  // dropout key
__device__ float g_h[2][2][64 * 512];                   // [dir][parity][b*512+d]
__device__ unsigned int g_ctr[2];                       // per-direction step barrier

// ---------------- JAX threefry2x32 (bit-exact, 20 rounds) ----------------
__device__ __forceinline__ uint32_t rotl32(uint32_t x, int r) { return (x << r) | (x >> (32 - r)); }

__device__ __forceinline__ void tf2x32(uint32_t k0, uint32_t k1, uint32_t& x0, uint32_t& x1) {
    uint32_t k2 = k0 ^ k1 ^ 0x1BD11BDAu;
    x0 += k0; x1 += k1;
#define TFR(r) { x0 += x1; x1 = rotl32(x1, r); x1 ^= x0; }
    TFR(13) TFR(15) TFR(26) TFR(6)   x0 += k1; x1 += k2 + 1u;
    TFR(17) TFR(29) TFR(16) TFR(24)  x0 += k2; x1 += k0 + 2u;
    TFR(13) TFR(15) TFR(26) TFR(6)   x0 += k0; x1 += k1 + 3u;
    TFR(17) TFR(29) TFR(16) TFR(24)  x0 += k1; x1 += k2 + 4u;
    TFR(13) TFR(15) TFR(26) TFR(6)   x0 += k2; x1 += k0 + 5u;
#undef TFR
}

// partitionable random_bits (32-bit): element i -> tf(key, (0, i)), bits = x0 ^ x1
__device__ __forceinline__ uint32_t pbits(uint32_t k0, uint32_t k1, uint32_t i) {
    uint32_t x0 = 0u, x1 = i;
    tf2x32(k0, k1, x0, x1);
    return x0 ^ x1;
}

__device__ __forceinline__ float u01(uint32_t bits) {
    return __uint_as_float((bits >> 9) | 0x3f800000u) - 1.0f;
}
__device__ __forceinline__ float sigm(float x) { return 1.0f / (1.0f + expf(-x)); }

// ---------------- K1: key derivation (fold-like split) + barrier reset ----------------
__global__ void rng_setup_kernel() {
    int tid = threadIdx.x;
    __shared__ uint32_t s[4];
    if (tid == 0) {
        g_ctr[0] = 0u; g_ctr[1] = 0u;
        uint32_t a, b;
        a = 0u; b = 0u; tf2x32(0u, 42u, a, b); g_kd = make_uint2(a, b);
        a = 0u; b = 1u; tf2x32(0u, 42u, a, b); s[0] = a; s[1] = b;   // kf
        a = 0u; b = 2u; tf2x32(0u, 42u, a, b); s[2] = a; s[3] = b;   // kb
    }
    __syncthreads();
    if (tid < 2) {
        uint32_t k0 = s[tid * 2], k1 = s[tid * 2 + 1];
        for (int t = 0; t < 1024; ++t) {
            uint32_t z0 = 0u, z1 = 0u; tf2x32(k0, k1, z0, z1);
            uint32_t n0 = 0u, n1 = 1u; tf2x32(k0, k1, n0, n1);
            g_kz[tid * 1024 + t] = make_uint2(z0, z1);
            k0 = n0; k1 = n1;
        }
    }
}

// ---------------- K2: vocab base table: base[dir][v][g] = embed[v] . W[:512][g] ----------------
__global__ void __launch_bounds__(256) base_kernel(const float* __restrict__ embed,
                                                   const float* __restrict__ Wf,
                                                   const float* __restrict__ Wb) {
    int dir = blockIdx.z;
    const float* W = dir ? Wb : Wf;
    int g = blockIdx.x * 256 + threadIdx.x;
    int v0 = blockIdx.y * 4;
    float acc0 = 0.f, acc1 = 0.f, acc2 = 0.f, acc3 = 0.f;
#pragma unroll 4
    for (int d = 0; d < 512; ++d) {
        float w = W[(size_t)d * 2048 + g];
        acc0 = fmaf(embed[(size_t)(v0 + 0) * 512 + d], w, acc0);
        acc1 = fmaf(embed[(size_t)(v0 + 1) * 512 + d], w, acc1);
        acc2 = fmaf(embed[(size_t)(v0 + 2) * 512 + d], w, acc2);
        acc3 = fmaf(embed[(size_t)(v0 + 3) * 512 + d], w, acc3);
    }
    g_base[dir][v0 + 0][g] = acc0;
    g_base[dir][v0 + 1][g] = acc1;
    g_base[dir][v0 + 2][g] = acc2;
    g_base[dir][v0 + 3][g] = acc3;
}

// ---------------- K3: dropout -> compact per-row dropped (d, e) lists ----------------
__global__ void __launch_bounds__(256) drop_kernel(const int* __restrict__ tokens,
                                                   const float* __restrict__ embed) {
    unsigned row = (blockIdx.x * 256u + threadIdx.x) >> 5;   // [0, 65536)
    int lane = threadIdx.x & 31;
    uint2 kd = g_kd;
    int tok = tokens[row];
    const float* erow = &embed[(size_t)tok * 512];
    uint2* outp = &g_dropPack[(size_t)row * 128];
    unsigned count = 0;
#pragma unroll 4
    for (int it = 0; it < 16; ++it) {
        int d = it * 32 + lane;
        uint32_t bits = pbits(kd.x, kd.y, row * 512u + (unsigned)d);
        bool dropped = !(u01(bits) < 0.9f);
        unsigned m = __ballot_sync(0xffffffffu, dropped);
        if (dropped) {
            unsigned pos = count + __popc(m & ((1u << lane) - 1u));
            outp[pos] = make_uint2((unsigned)d, __float_as_uint(erow[d]));
        }
        count += __popc(m);
    }
    if (lane == 0) g_dropN[row] = count;
}

// ---------------- K4: zoneout mask precompute ----------------
__global__ void zoneout_kernel() {
    size_t gi = (size_t)blockIdx.x * 256 + threadIdx.x;    // [0, 2*1024*32768)
    unsigned pair = (unsigned)(gi & 32767u);
    unsigned st = (unsigned)(gi >> 15);                    // dir*1024 + s
    uint2 k = g_kz[st];
    uint32_t bh = pbits(k.x, k.y, pair);
    uint32_t bc = pbits(k.x, k.y, pair + 32768u);
    g_zb[gi] = (unsigned char)(((u01(bh) < 0.1f) ? 1u : 0u) | ((u01(bc) < 0.1f) ? 2u : 0u));
}

// ---------------- K5: projection via base table + sparse dropout correction ----------------
// pre[t][b][g] = (base[tok] - sum_dropped e_d * W[d][g]) / 0.9 + bias[g]
// CTA: (dir, 64-col slice); SMEM holds W[0:512][g0:g0+64] (128KB). Warp = one row at a time.
#define CORR_SMEM (512 * 64 * 4)

__global__ void __launch_bounds__(256, 1) proj_corr_kernel(const int* __restrict__ tokens,
                                                           const float* __restrict__ Wf,
                                                           const float* __restrict__ Wb,
                                                           const float* __restrict__ bf,
                                                           const float* __restrict__ bb) {
    extern __shared__ float sW[];   // [512][64]
    int dir = blockIdx.x >> 5;
    int slice = blockIdx.x & 31;
    int g0 = slice * 64;
    const float* W = dir ? Wb : Wf;
    const float* bias = dir ? bb : bf;
    float* pre = dir ? g_preB : g_preF;
    const float* base = &g_base[dir][0][0];
    int tid = threadIdx.x;

    for (int i = tid; i < 512 * 64; i += 256)
        sW[i] = W[(size_t)(i >> 6) * 2048 + g0 + (i & 63)];
    __syncthreads();

    int lane = tid & 31, w = tid >> 5;
    float2 bv = *(const float2*)&bias[g0 + lane * 2];
    int rEnd = blockIdx.y * 32768 + 32768;
    for (int r = blockIdx.y * 32768 + w; r < rEnd; r += 8) {
        int tok = tokens[r];
        float2 acc = *(const float2*)&base[(size_t)tok * 2048 + g0 + lane * 2];
        unsigned n = g_dropN[r];
        const uint2* lst = &g_dropPack[(size_t)r * 128];
#pragma unroll 4
        for (unsigned j = 0; j < n; ++j) {
            uint2 e = lst[j];
            float val = __uint_as_float(e.y);
            float2 wv = *(const float2*)&sW[e.x * 64 + lane * 2];
            acc.x = fmaf(-val, wv.x, acc.x);
            acc.y = fmaf(-val, wv.y, acc.y);
        }
        int b = r >> 10, t = r & 1023;
        float2 o;
        o.x = fmaf(acc.x, (1.0f / 0.9f), bv.x);
        o.y = fmaf(acc.y, (1.0f / 0.9f), bv.y);
        *(float2*)&pre[(((size_t)t * 64) + b) * 2048 + g0 + lane * 2] = o;
    }
}

// ---------------- K6: persistent bidirectional LSTM scan (FFMA2 matvec) ----------------
#define SH_STRIDE 516
#define SCAN_SMEM ((32 * 512 + 64 * SH_STRIDE) * 4)

__global__ void __launch_bounds__(256, 1) scan_kernel(const int* __restrict__ lengths,
                                                      const float* __restrict__ Wf,
                                                      const float* __restrict__ Wb,
                                                      float* __restrict__ out) {
    extern __shared__ float smem[];
    float* sWT = smem;                 // 32*512
    float* sH = smem + 32 * 512;       // 64*516
    __shared__ int sLen[64];

    int dir = blockIdx.x >> 6, cta = blockIdx.x & 63, d0 = cta * 8;
    int tid = threadIdx.x;
    const float* W = dir ? Wb : Wf;

    for (int idx = tid; idx < 32 * 512; idx += 256) {
        int j = idx >> 9, k = idx & 511;
        sWT[idx] = W[(size_t)(512 + k) * 2048 + ((j >> 3) << 9) + d0 + (j & 7)];
    }
    if (tid < 64) sLen[tid] = lengths[tid];

    int q = tid >> 6, b = tid & 63;
    int dd = q * 2, d = d0 + dd;
    float c0r = 0.f, c1r = 0.f;
    volatile unsigned int* ctr = &g_ctr[dir];
    const float* pre = dir ? g_preB : g_preF;
    const unsigned char* zbase = &g_zb[(size_t)dir * 1024 * 32768];
    __syncthreads();

    for (int s = 0; s < 1024; ++s) {
        int tx = dir ? (1023 - s) : s;
        // ---- stage h (with bwd ResetCore) ----
        if (s == 0) {
            for (int i = tid * 4; i < 32768; i += 1024)
                *(float4*)&sH[(i >> 9) * SH_STRIDE + (i & 511)] = make_float4(0, 0, 0, 0);
        } else {
            const float* hg = g_h[dir][s & 1];
            for (int i = tid * 4; i < 32768; i += 1024) {
                int hb = i >> 9, hd = i & 511;
                float4 v = __ldcg((const float4*)&hg[i]);
                if (dir && (1023 - s) < sLen[hb] - 1) v = make_float4(0, 0, 0, 0);
                *(float4*)&sH[hb * SH_STRIDE + hd] = v;
            }
        }
        __syncthreads();

        // ---- prefetch x-projection + zoneout bits ----
        size_t prow = ((size_t)tx * 64 + b) * 2048 + (size_t)d;
        float2 pxi = *(const float2*)&pre[prow];
        float2 pxg = *(const float2*)&pre[prow + 512];
        float2 pxf = *(const float2*)&pre[prow + 1024];
        float2 pxo = *(const float2*)&pre[prow + 1536];
        const unsigned char* zp = &zbase[((size_t)s << 15) + b * 512 + d];
        unsigned char z0 = zp[0], z1 = zp[1];

        // ---- h @ W_h slice: 8 gate pre-activations via packed f32x2 FMA ----
        unsigned long long acc2[8];
#pragma unroll
        for (int u = 0; u < 8; ++u) acc2[u] = 0ull;
        const float* hrow = &sH[b * SH_STRIDE];
#pragma unroll 2
        for (int k = 0; k < 512; k += 4) {
            float4 hv = *(const float4*)&hrow[k];
            unsigned long long h01, h23;
            asm("mov.b64 %0, {%1,%2};" : "=l"(h01) : "f"(hv.x), "f"(hv.y));
            asm("mov.b64 %0, {%1,%2};" : "=l"(h23) : "f"(hv.z), "f"(hv.w));
#pragma unroll
            for (int u = 0; u < 8; ++u) {
                const float4 wv = *(const float4*)&sWT[((u >> 1) * 8 + dd + (u & 1)) * 512 + k];
                unsigned long long w01, w23;
                asm("mov.b64 %0, {%1,%2};" : "=l"(w01) : "f"(wv.x), "f"(wv.y));
                asm("mov.b64 %0, {%1,%2};" : "=l"(w23) : "f"(wv.z), "f"(wv.w));
                asm("fma.rn.f32x2 %0, %1, %2, %0;" : "+l"(acc2[u]) : "l"(h01), "l"(w01));
                asm("fma.rn.f32x2 %0, %1, %2, %0;" : "+l"(acc2[u]) : "l"(h23), "l"(w23));
            }
        }
        float acc[8];
#pragma unroll
        for (int u = 0; u < 8; ++u) {
            float lo, hi;
            asm("mov.b64 {%0,%1}, %2;" : "=f"(lo), "=f"(hi) : "l"(acc2[u]));
            acc[u] = lo + hi;
        }

        // ---- gates + zoneout ----
        if (dir && (1023 - s) < sLen[b] - 1) { c0r = 0.f; c1r = 0.f; }
        float i0 = pxi.x + acc[0], i1 = pxi.y + acc[1];
        float gg0 = pxg.x + acc[2], gg1 = pxg.y + acc[3];
        float f0 = sigm(pxf.x + acc[4] + 1.f), f1 = sigm(pxf.y + acc[5] + 1.f);
        float o0 = sigm(pxo.x + acc[6]), o1 = sigm(pxo.y + acc[7]);
        float cn0 = f0 * c0r + sigm(i0) * tanhf(gg0);
        float cn1 = f1 * c1r + sigm(i1) * tanhf(gg1);
        float hn0 = o0 * tanhf(cn0);
        float hn1 = o1 * tanhf(cn1);
        float hp0 = hrow[d], hp1 = hrow[d + 1];
        float ho0 = (z0 & 1) ? hp0 : hn0;
        float ho1 = (z1 & 1) ? hp1 : hn1;
        c0r = (z0 & 2) ? c0r : cn0;
        c1r = (z1 & 2) ? c1r : cn1;

        // ---- write h (for next step) + output ----
        float* hw = g_h[dir][(s + 1) & 1];
        float2 hv2 = make_float2(ho0, ho1);
        __stcg((float2*)&hw[b * 512 + d], hv2);
        *(float2*)&out[(((size_t)b << 10) + tx) * 1024 + ((size_t)dir << 9) + d] = hv2;

        // ---- per-direction grid barrier ----
        __syncthreads();
        if (s < 1023) {
            if (tid == 0) {
                __threadfence();
                atomicAdd((unsigned int*)ctr, 1u);
                unsigned int target = 64u * (unsigned)(s + 1);
                while (*ctr < target) __nanosleep(64);
                __threadfence();
            }
            __syncthreads();
        }
    }
}

// ---------------- launch ----------------
extern "C" void kernel_launch(void* const* d_in, const int* in_sizes, int n_in,
                              void* d_out, int out_size) {
    (void)in_sizes; (void)n_in; (void)out_size;
    const int*   tokens  = (const int*)d_in[0];
    const int*   lengths = (const int*)d_in[1];
    const float* embed   = (const float*)d_in[2];
    const float* Wf      = (const float*)d_in[3];
    const float* bf      = (const float*)d_in[4];
    const float* Wb      = (const float*)d_in[5];
    const float* bb      = (const float*)d_in[6];
    float* out = (float*)d_out;

    cudaFuncSetAttribute(scan_kernel, cudaFuncAttributeMaxDynamicSharedMemorySize, SCAN_SMEM);
    cudaFuncSetAttribute(proj_corr_kernel, cudaFuncAttributeMaxDynamicSharedMemorySize, CORR_SMEM);

    rng_setup_kernel<<<1, 64>>>();
    base_kernel<<<dim3(8, 64, 2), 256>>>(embed, Wf, Wb);
    drop_kernel<<<8192, 256>>>(tokens, embed);
    zoneout_kernel<<<(2u * 1024u * 32768u) / 256u, 256>>>();
    proj_corr_kernel<<<dim3(64, 2), 256, CORR_SMEM>>>(tokens, Wf, Wb, bf, bb);
    scan_kernel<<<128, 256, SCAN_SMEM>>>(lengths, Wf, Wb, out);
}